// round 10
// baseline (speedup 1.0000x reference)
#include <cuda_runtime.h>
#include <cuda_bf16.h>
#include <stdint.h>

#define NN 256            // N (atoms per batch)
#define MAXB 512          // max batch
#define GR 32             // output rows per gather block

__device__ int       g_perm[MAXB * NN];
__device__ float     g_ss1[MAXB * NN], g_v41[MAXB * NN];
__device__ long long g_vi1[MAXB * NN];
__device__ float     g_ss2[MAXB * NN], g_v42[MAXB * NN];
__device__ long long g_vi2[MAXB * NN];

// ---------------------------------------------------------------------------
// Reduction: each thread owns 4 columns (float4 loads), unroll k by 8 with
// FRONT-BATCHED loads (8 independent LDG.128 in flight before any math).
// Three voters per column; seq and IC4 orders BIT-IDENTICAL to the passing
// R7-R9 kernels; truth voter = exact fixed-point int64 (order-free).
// Grid (B, 2): blockIdx.y selects D1 or D2.
// ---------------------------------------------------------------------------
__global__ __launch_bounds__(64) void colsum_kernel(const float* __restrict__ D1,
                                                    const float* __restrict__ D2) {
    const int b     = blockIdx.x;
    const int which = blockIdx.y;
    const int t     = threadIdx.x;

    const float4* q = (const float4*)((which ? D2 : D1) + (size_t)b * NN * NN);
    float*     oss = (which ? g_ss2 : g_ss1) + b * NN;
    float*     ov4 = (which ? g_v42 : g_v41) + b * NN;
    long long* ovi = (which ? g_vi2 : g_vi1) + b * NN;

    float ss[4], a[4][4];
    long long acc[4];
#pragma unroll
    for (int c = 0; c < 4; ++c) {
        ss[c] = 0.f; acc[c] = 0;
#pragma unroll
        for (int m = 0; m < 4; ++m) a[c][m] = 0.f;
    }

    const float SCALE = 1099511627776.0f;   // 2^40 (exact power-of-two scale)

    for (int k = 0; k < NN; k += 8) {
        // Front-batched loads: 8 independent LDG.128 (128 B in flight/thread).
        float4 v[8];
#pragma unroll
        for (int m = 0; m < 8; ++m)
            v[m] = q[(size_t)(k + m) * 64 + t];

        float x[8][4];
#pragma unroll
        for (int m = 0; m < 8; ++m) {
            x[m][0] = v[m].x; x[m][1] = v[m].y;
            x[m][2] = v[m].z; x[m][3] = v[m].w;
        }

#pragma unroll
        for (int c = 0; c < 4; ++c) {
            // strict sequential chain over k (identical order to R7-R9)
            float s = ss[c];
#pragma unroll
            for (int m = 0; m < 8; ++m) s = __fadd_rn(s, x[m][c]);
            ss[c] = s;
            // IC4 round-robin accumulators: a[m] gets k%4==m elements in
            // increasing-k order (identical to R7-R9)
#pragma unroll
            for (int m = 0; m < 4; ++m) {
                a[c][m] = __fadd_rn(a[c][m], x[m][c]);
                a[c][m] = __fadd_rn(a[c][m], x[m + 4][c]);
            }
            // exact fixed-point truth (order-free, ALU pipe)
#pragma unroll
            for (int m = 0; m < 8; ++m)
                acc[c] += __float2ll_rn(x[m][c] * SCALE);
        }
    }

    const int col = 4 * t;
#pragma unroll
    for (int c = 0; c < 4; ++c) {
        oss[col + c] = ss[c];
        ov4[col + c] = __fadd_rn(__fadd_rn(__fadd_rn(a[c][0], a[c][1]),
                                           a[c][2]), a[c][3]);
        ovi[col + c] = acc[c];
    }
}

// ---------------------------------------------------------------------------
// Sort: bitonic lexsort per batch with majority comparator over the three
// voter orders (type primary; per-voter index tie-break). Also writes the
// gathered-types output tail.
// ---------------------------------------------------------------------------
__global__ void sort_kernel(const int* __restrict__ t1,
                            const int* __restrict__ t2,
                            float* __restrict__ out,
                            long long base, long long out_size) {
    const int b   = blockIdx.x;
    const int tid = threadIdx.x;

    __shared__ float     vs1[NN], v41[NN];
    __shared__ long long vi1[NN];
    __shared__ float     vs2[NN], v42[NN];
    __shared__ long long vi2[NN];
    __shared__ int       ty1s[NN], ty2s[NN];
    __shared__ int       idx1[NN], idx2[NN];

    vs1[tid] = g_ss1[b * NN + tid];
    v41[tid] = g_v41[b * NN + tid];
    vi1[tid] = g_vi1[b * NN + tid];
    vs2[tid] = g_ss2[b * NN + tid];
    v42[tid] = g_v42[b * NN + tid];
    vi2[tid] = g_vi2[b * NN + tid];
    ty1s[tid] = t1[b * NN + tid];
    ty2s[tid] = t2[b * NN + tid];
    idx1[tid] = tid;
    idx2[tid] = tid;
    __syncthreads();

    #define BEFORE(ty, vsq, v4a, vib, i, j, res)                              \
        {                                                                     \
            int _ti = ty[i], _tj = ty[j];                                     \
            if (_ti != _tj) { res = (_ti < _tj); }                            \
            else {                                                            \
                int _v = 0;                                                   \
                _v += (vsq[i] < vsq[j]) || (vsq[i] == vsq[j] && (i) < (j));   \
                _v += (v4a[i] < v4a[j]) || (v4a[i] == v4a[j] && (i) < (j));   \
                _v += (vib[i] < vib[j]) || (vib[i] == vib[j] && (i) < (j));   \
                res = (_v >= 2);                                              \
            }                                                                 \
        }

    for (int k = 2; k <= NN; k <<= 1) {
        for (int j = k >> 1; j > 0; j >>= 1) {
            int partner = tid ^ j;
            if (partner > tid) {
                bool up = ((tid & k) == 0);
                {
                    int ia = idx1[tid], ib = idx1[partner];
                    bool a_before_b;
                    BEFORE(ty1s, vs1, v41, vi1, ia, ib, a_before_b);
                    if (up == !a_before_b) { idx1[tid] = ib; idx1[partner] = ia; }
                }
                {
                    int ia = idx2[tid], ib = idx2[partner];
                    bool a_before_b;
                    BEFORE(ty2s, vs2, v42, vi2, ia, ib, a_before_b);
                    if (up == !a_before_b) { idx2[tid] = ib; idx2[partner] = ia; }
                }
            }
            __syncthreads();
        }
    }
    #undef BEFORE

    // perm[order2[t]] = order1[t]
    g_perm[b * NN + idx2[tid]] = idx1[tid];

    // gathered-types tail: out[base + b*NN + pos] = types1[source atom]
    long long o = base + (long long)b * NN + idx2[tid];
    if (o < out_size) out[o] = (float)ty1s[idx1[tid]];
}

// ---------------------------------------------------------------------------
// Gather: out[b,i,j] = D1[b, perm[i], perm[j]]. GR rows per block; float4
// loads AND float4 stores (4 shared gathers per 16B store).
// ---------------------------------------------------------------------------
__global__ void gather_kernel(const float* __restrict__ D1,
                              float* __restrict__ out) {
    const int b   = blockIdx.y;
    const int i0  = blockIdx.x * GR;
    const int tid = threadIdx.x;   // 256 threads

    __shared__ int   sp[NN];
    __shared__ float sd[GR][NN];

    sp[tid] = g_perm[b * NN + tid];
    __syncthreads();

    const float4* src4 = (const float4*)(D1 + (size_t)b * NN * NN);
#pragma unroll
    for (int m = 0; m < GR * 64 / 256; ++m) {
        int q  = m * 256 + tid;     // over GR*64 float4 slots
        int r  = q >> 6;            // row
        int c4 = q & 63;
        int s  = sp[i0 + r];
        ((float4*)sd[r])[c4] = src4[(size_t)s * 64 + c4];
    }
    __syncthreads();

    float4* ob = (float4*)(out + ((size_t)b * NN + i0) * NN);
#pragma unroll
    for (int m = 0; m < GR * 64 / 256; ++m) {
        int q  = m * 256 + tid;
        int r  = q >> 6;
        int c4 = q & 63;
        float4 v;
        v.x = sd[r][sp[c4 * 4 + 0]];
        v.y = sd[r][sp[c4 * 4 + 1]];
        v.z = sd[r][sp[c4 * 4 + 2]];
        v.w = sd[r][sp[c4 * 4 + 3]];
        ob[(size_t)r * 64 + c4] = v;
    }
}

extern "C" void kernel_launch(void* const* d_in, const int* in_sizes, int n_in,
                              void* d_out, int out_size) {
    const float* D1 = (const float*)d_in[0];
    const float* D2 = (const float*)d_in[1];
    const int*   t1 = (const int*)d_in[2];
    const int*   t2 = (const int*)d_in[3];
    float* out = (float*)d_out;

    int B = in_sizes[0] / (NN * NN);
    if (B > MAXB) B = MAXB;

    dim3 cgr(B, 2);
    colsum_kernel<<<cgr, 64>>>(D1, D2);

    long long base = (long long)B * NN * NN;
    sort_kernel<<<B, NN>>>(t1, t2, out, base, (long long)out_size);

    dim3 ggrid(NN / GR, B);
    gather_kernel<<<ggrid, 256>>>(D1, out);
}

// round 11
// speedup vs baseline: 1.0142x; 1.0142x over previous
#include <cuda_runtime.h>
#include <cuda_bf16.h>
#include <stdint.h>

#define NN 256            // N (atoms per batch)
#define MAXB 512          // max batch
#define GR 16             // output rows per gather block

__device__ int       g_perm[MAXB * NN];
__device__ float     g_ss1[MAXB * NN], g_v41[MAXB * NN];
__device__ long long g_vi1[MAXB * NN];
__device__ float     g_ss2[MAXB * NN], g_v42[MAXB * NN];
__device__ long long g_vi2[MAXB * NN];

// ---------------------------------------------------------------------------
// Reduction: each thread owns 4 columns. Per k-octet, 8 LDG.128 issued via
// asm volatile (ptxas cannot reorder/sink volatile asm relative to each
// other) -> 128B genuinely in flight per thread. Voters bit-identical to the
// passing R7-R9 kernels: seq chain, IC4 round-robin, exact int64 fixed-point.
// Grid (B, 2): blockIdx.y selects D1 or D2.
// ---------------------------------------------------------------------------
__global__ __launch_bounds__(64) void colsum_kernel(const float* __restrict__ D1,
                                                    const float* __restrict__ D2) {
    const int b     = blockIdx.x;
    const int which = blockIdx.y;
    const int t     = threadIdx.x;

    const float4* q = (const float4*)((which ? D2 : D1) + (size_t)b * NN * NN) + t;
    float*     oss = (which ? g_ss2 : g_ss1) + b * NN;
    float*     ov4 = (which ? g_v42 : g_v41) + b * NN;
    long long* ovi = (which ? g_vi2 : g_vi1) + b * NN;

    float ss[4], a[4][4];
    long long acc[4];
#pragma unroll
    for (int c = 0; c < 4; ++c) {
        ss[c] = 0.f; acc[c] = 0;
#pragma unroll
        for (int m = 0; m < 4; ++m) a[c][m] = 0.f;
    }

    const float SCALE = 1099511627776.0f;   // 2^40 (exact power-of-two scale)

#pragma unroll 1
    for (int k = 0; k < NN; k += 8) {
        // 8 back-to-back LDG.128 via volatile asm (un-reorderable).
        float x[8][4];
#pragma unroll
        for (int m = 0; m < 8; ++m) {
            asm volatile("ld.global.nc.v4.f32 {%0, %1, %2, %3}, [%4];"
                         : "=f"(x[m][0]), "=f"(x[m][1]),
                           "=f"(x[m][2]), "=f"(x[m][3])
                         : "l"(q + (size_t)(k + m) * 64));
        }

#pragma unroll
        for (int c = 0; c < 4; ++c) {
            // strict sequential chain over k (identical order to R7-R9)
            float s = ss[c];
#pragma unroll
            for (int m = 0; m < 8; ++m) s = __fadd_rn(s, x[m][c]);
            ss[c] = s;
            // IC4 round-robin: a[m] receives k%4==m elements in increasing k
#pragma unroll
            for (int m = 0; m < 4; ++m) {
                a[c][m] = __fadd_rn(a[c][m], x[m][c]);
                a[c][m] = __fadd_rn(a[c][m], x[m + 4][c]);
            }
            // exact fixed-point truth (order-free, ALU pipe)
#pragma unroll
            for (int m = 0; m < 8; ++m)
                acc[c] += __float2ll_rn(x[m][c] * SCALE);
        }
    }

    const int col = 4 * t;
#pragma unroll
    for (int c = 0; c < 4; ++c) {
        oss[col + c] = ss[c];
        ov4[col + c] = __fadd_rn(__fadd_rn(__fadd_rn(a[c][0], a[c][1]),
                                           a[c][2]), a[c][3]);
        ovi[col + c] = acc[c];
    }
}

// ---------------------------------------------------------------------------
// Sort: bitonic lexsort per batch with majority comparator over the three
// voter orders (type primary; per-voter index tie-break). Also writes the
// gathered-types output tail.
// ---------------------------------------------------------------------------
__global__ void sort_kernel(const int* __restrict__ t1,
                            const int* __restrict__ t2,
                            float* __restrict__ out,
                            long long base, long long out_size) {
    const int b   = blockIdx.x;
    const int tid = threadIdx.x;

    __shared__ float     vs1[NN], v41[NN];
    __shared__ long long vi1[NN];
    __shared__ float     vs2[NN], v42[NN];
    __shared__ long long vi2[NN];
    __shared__ int       ty1s[NN], ty2s[NN];
    __shared__ int       idx1[NN], idx2[NN];

    vs1[tid] = g_ss1[b * NN + tid];
    v41[tid] = g_v41[b * NN + tid];
    vi1[tid] = g_vi1[b * NN + tid];
    vs2[tid] = g_ss2[b * NN + tid];
    v42[tid] = g_v42[b * NN + tid];
    vi2[tid] = g_vi2[b * NN + tid];
    ty1s[tid] = t1[b * NN + tid];
    ty2s[tid] = t2[b * NN + tid];
    idx1[tid] = tid;
    idx2[tid] = tid;
    __syncthreads();

    #define BEFORE(ty, vsq, v4a, vib, i, j, res)                              \
        {                                                                     \
            int _ti = ty[i], _tj = ty[j];                                     \
            if (_ti != _tj) { res = (_ti < _tj); }                            \
            else {                                                            \
                int _v = 0;                                                   \
                _v += (vsq[i] < vsq[j]) || (vsq[i] == vsq[j] && (i) < (j));   \
                _v += (v4a[i] < v4a[j]) || (v4a[i] == v4a[j] && (i) < (j));   \
                _v += (vib[i] < vib[j]) || (vib[i] == vib[j] && (i) < (j));   \
                res = (_v >= 2);                                              \
            }                                                                 \
        }

    for (int k = 2; k <= NN; k <<= 1) {
        for (int j = k >> 1; j > 0; j >>= 1) {
            int partner = tid ^ j;
            if (partner > tid) {
                bool up = ((tid & k) == 0);
                {
                    int ia = idx1[tid], ib = idx1[partner];
                    bool a_before_b;
                    BEFORE(ty1s, vs1, v41, vi1, ia, ib, a_before_b);
                    if (up == !a_before_b) { idx1[tid] = ib; idx1[partner] = ia; }
                }
                {
                    int ia = idx2[tid], ib = idx2[partner];
                    bool a_before_b;
                    BEFORE(ty2s, vs2, v42, vi2, ia, ib, a_before_b);
                    if (up == !a_before_b) { idx2[tid] = ib; idx2[partner] = ia; }
                }
            }
            __syncthreads();
        }
    }
    #undef BEFORE

    // perm[order2[t]] = order1[t]
    g_perm[b * NN + idx2[tid]] = idx1[tid];

    // gathered-types tail: out[base + b*NN + pos] = types1[source atom]
    long long o = base + (long long)b * NN + idx2[tid];
    if (o < out_size) out[o] = (float)ty1s[idx1[tid]];
}

// ---------------------------------------------------------------------------
// Gather: out[b,i,j] = D1[b, perm[i], perm[j]]. GR rows per block; float4
// loads AND float4 stores (4 shared gathers per 16B store).
// ---------------------------------------------------------------------------
__global__ void gather_kernel(const float* __restrict__ D1,
                              float* __restrict__ out) {
    const int b   = blockIdx.y;
    const int i0  = blockIdx.x * GR;
    const int tid = threadIdx.x;   // 256 threads

    __shared__ int   sp[NN];
    __shared__ float sd[GR][NN];

    sp[tid] = g_perm[b * NN + tid];
    __syncthreads();

    const float4* src4 = (const float4*)(D1 + (size_t)b * NN * NN);
#pragma unroll
    for (int m = 0; m < GR * 64 / 256; ++m) {
        int q  = m * 256 + tid;     // over GR*64 float4 slots
        int r  = q >> 6;            // row
        int c4 = q & 63;
        int s  = sp[i0 + r];
        ((float4*)sd[r])[c4] = src4[(size_t)s * 64 + c4];
    }
    __syncthreads();

    float4* ob = (float4*)(out + ((size_t)b * NN + i0) * NN);
#pragma unroll
    for (int m = 0; m < GR * 64 / 256; ++m) {
        int q  = m * 256 + tid;
        int r  = q >> 6;
        int c4 = q & 63;
        float4 v;
        v.x = sd[r][sp[c4 * 4 + 0]];
        v.y = sd[r][sp[c4 * 4 + 1]];
        v.z = sd[r][sp[c4 * 4 + 2]];
        v.w = sd[r][sp[c4 * 4 + 3]];
        ob[(size_t)r * 64 + c4] = v;
    }
}

extern "C" void kernel_launch(void* const* d_in, const int* in_sizes, int n_in,
                              void* d_out, int out_size) {
    const float* D1 = (const float*)d_in[0];
    const float* D2 = (const float*)d_in[1];
    const int*   t1 = (const int*)d_in[2];
    const int*   t2 = (const int*)d_in[3];
    float* out = (float*)d_out;

    int B = in_sizes[0] / (NN * NN);
    if (B > MAXB) B = MAXB;

    dim3 cgr(B, 2);
    colsum_kernel<<<cgr, 64>>>(D1, D2);

    long long base = (long long)B * NN * NN;
    sort_kernel<<<B, NN>>>(t1, t2, out, base, (long long)out_size);

    dim3 ggrid(NN / GR, B);
    gather_kernel<<<ggrid, 256>>>(D1, out);
}

// round 12
// speedup vs baseline: 1.0151x; 1.0008x over previous
#include <cuda_runtime.h>
#include <cuda_bf16.h>
#include <stdint.h>

#define NN 256            // N (atoms per batch)
#define MAXB 512          // max batch
#define GR 16             // output rows per gather block

__device__ int       g_perm[MAXB * NN];
__device__ float     g_ss1[MAXB * NN], g_v41[MAXB * NN];
__device__ long long g_vi1[MAXB * NN];
__device__ float     g_ss2[MAXB * NN], g_v42[MAXB * NN];
__device__ long long g_vi2[MAXB * NN];

// ---------------------------------------------------------------------------
// Reduction: ONE column per thread (scalar loads, warp = one 128B line per k).
// 256 threads/block, grid (B, 2) -> 8192 warps chip-wide (~55/SM) instead of
// the float4 layout's 2048 (latency-bound at 2.2 TB/s for three rounds).
// Voters bit-identical to the passing R7-R11 kernels:
//   seq  : strict sequential chain over k
//   IC4  : a[k%4] accumulators in increasing k, left-chain combine
//   truth: exact fixed-point int64 (order-free)
// ---------------------------------------------------------------------------
__global__ __launch_bounds__(256) void colsum_kernel(const float* __restrict__ D1,
                                                     const float* __restrict__ D2) {
    const int b     = blockIdx.x;
    const int which = blockIdx.y;
    const int tid   = threadIdx.x;

    const float* p = ((which ? D2 : D1) + (size_t)b * NN * NN) + tid;
    float*     oss = (which ? g_ss2 : g_ss1) + b * NN;
    float*     ov4 = (which ? g_v42 : g_v41) + b * NN;
    long long* ovi = (which ? g_vi2 : g_vi1) + b * NN;

    float ss = 0.f, a0 = 0.f, a1 = 0.f, a2 = 0.f, a3 = 0.f;
    long long acc = 0;
    const float SCALE = 1099511627776.0f;   // 2^40 (exact power-of-two scale)

#pragma unroll 1
    for (int k = 0; k < NN; k += 8) {
        float x0 = __ldg(p + (size_t)(k + 0) * NN);
        float x1 = __ldg(p + (size_t)(k + 1) * NN);
        float x2 = __ldg(p + (size_t)(k + 2) * NN);
        float x3 = __ldg(p + (size_t)(k + 3) * NN);
        float x4 = __ldg(p + (size_t)(k + 4) * NN);
        float x5 = __ldg(p + (size_t)(k + 5) * NN);
        float x6 = __ldg(p + (size_t)(k + 6) * NN);
        float x7 = __ldg(p + (size_t)(k + 7) * NN);

        // strict sequential chain (identical order to R7-R11)
        ss = __fadd_rn(ss, x0); ss = __fadd_rn(ss, x1);
        ss = __fadd_rn(ss, x2); ss = __fadd_rn(ss, x3);
        ss = __fadd_rn(ss, x4); ss = __fadd_rn(ss, x5);
        ss = __fadd_rn(ss, x6); ss = __fadd_rn(ss, x7);

        // IC4 round-robin: a[m] receives k%4==m elements in increasing k
        a0 = __fadd_rn(a0, x0); a1 = __fadd_rn(a1, x1);
        a2 = __fadd_rn(a2, x2); a3 = __fadd_rn(a3, x3);
        a0 = __fadd_rn(a0, x4); a1 = __fadd_rn(a1, x5);
        a2 = __fadd_rn(a2, x6); a3 = __fadd_rn(a3, x7);

        // exact fixed-point truth (order-free, ALU pipe)
        acc += __float2ll_rn(x0 * SCALE); acc += __float2ll_rn(x1 * SCALE);
        acc += __float2ll_rn(x2 * SCALE); acc += __float2ll_rn(x3 * SCALE);
        acc += __float2ll_rn(x4 * SCALE); acc += __float2ll_rn(x5 * SCALE);
        acc += __float2ll_rn(x6 * SCALE); acc += __float2ll_rn(x7 * SCALE);
    }

    oss[tid] = ss;
    ov4[tid] = __fadd_rn(__fadd_rn(__fadd_rn(a0, a1), a2), a3);
    ovi[tid] = acc;
}

// ---------------------------------------------------------------------------
// Sort: bitonic lexsort per batch with majority comparator over the three
// voter orders (type primary; per-voter index tie-break). Also writes the
// gathered-types output tail.
// ---------------------------------------------------------------------------
__global__ void sort_kernel(const int* __restrict__ t1,
                            const int* __restrict__ t2,
                            float* __restrict__ out,
                            long long base, long long out_size) {
    const int b   = blockIdx.x;
    const int tid = threadIdx.x;

    __shared__ float     vs1[NN], v41[NN];
    __shared__ long long vi1[NN];
    __shared__ float     vs2[NN], v42[NN];
    __shared__ long long vi2[NN];
    __shared__ int       ty1s[NN], ty2s[NN];
    __shared__ int       idx1[NN], idx2[NN];

    vs1[tid] = g_ss1[b * NN + tid];
    v41[tid] = g_v41[b * NN + tid];
    vi1[tid] = g_vi1[b * NN + tid];
    vs2[tid] = g_ss2[b * NN + tid];
    v42[tid] = g_v42[b * NN + tid];
    vi2[tid] = g_vi2[b * NN + tid];
    ty1s[tid] = t1[b * NN + tid];
    ty2s[tid] = t2[b * NN + tid];
    idx1[tid] = tid;
    idx2[tid] = tid;
    __syncthreads();

    #define BEFORE(ty, vsq, v4a, vib, i, j, res)                              \
        {                                                                     \
            int _ti = ty[i], _tj = ty[j];                                     \
            if (_ti != _tj) { res = (_ti < _tj); }                            \
            else {                                                            \
                int _v = 0;                                                   \
                _v += (vsq[i] < vsq[j]) || (vsq[i] == vsq[j] && (i) < (j));   \
                _v += (v4a[i] < v4a[j]) || (v4a[i] == v4a[j] && (i) < (j));   \
                _v += (vib[i] < vib[j]) || (vib[i] == vib[j] && (i) < (j));   \
                res = (_v >= 2);                                              \
            }                                                                 \
        }

    for (int k = 2; k <= NN; k <<= 1) {
        for (int j = k >> 1; j > 0; j >>= 1) {
            int partner = tid ^ j;
            if (partner > tid) {
                bool up = ((tid & k) == 0);
                {
                    int ia = idx1[tid], ib = idx1[partner];
                    bool a_before_b;
                    BEFORE(ty1s, vs1, v41, vi1, ia, ib, a_before_b);
                    if (up == !a_before_b) { idx1[tid] = ib; idx1[partner] = ia; }
                }
                {
                    int ia = idx2[tid], ib = idx2[partner];
                    bool a_before_b;
                    BEFORE(ty2s, vs2, v42, vi2, ia, ib, a_before_b);
                    if (up == !a_before_b) { idx2[tid] = ib; idx2[partner] = ia; }
                }
            }
            __syncthreads();
        }
    }
    #undef BEFORE

    // perm[order2[t]] = order1[t]
    g_perm[b * NN + idx2[tid]] = idx1[tid];

    // gathered-types tail: out[base + b*NN + pos] = types1[source atom]
    long long o = base + (long long)b * NN + idx2[tid];
    if (o < out_size) out[o] = (float)ty1s[idx1[tid]];
}

// ---------------------------------------------------------------------------
// Gather: out[b,i,j] = D1[b, perm[i], perm[j]]. GR rows per block; float4
// loads AND float4 stores (4 shared gathers per 16B store).
// ---------------------------------------------------------------------------
__global__ void gather_kernel(const float* __restrict__ D1,
                              float* __restrict__ out) {
    const int b   = blockIdx.y;
    const int i0  = blockIdx.x * GR;
    const int tid = threadIdx.x;   // 256 threads

    __shared__ int   sp[NN];
    __shared__ float sd[GR][NN];

    sp[tid] = g_perm[b * NN + tid];
    __syncthreads();

    const float4* src4 = (const float4*)(D1 + (size_t)b * NN * NN);
#pragma unroll
    for (int m = 0; m < GR * 64 / 256; ++m) {
        int q  = m * 256 + tid;     // over GR*64 float4 slots
        int r  = q >> 6;            // row
        int c4 = q & 63;
        int s  = sp[i0 + r];
        ((float4*)sd[r])[c4] = src4[(size_t)s * 64 + c4];
    }
    __syncthreads();

    float4* ob = (float4*)(out + ((size_t)b * NN + i0) * NN);
#pragma unroll
    for (int m = 0; m < GR * 64 / 256; ++m) {
        int q  = m * 256 + tid;
        int r  = q >> 6;
        int c4 = q & 63;
        float4 v;
        v.x = sd[r][sp[c4 * 4 + 0]];
        v.y = sd[r][sp[c4 * 4 + 1]];
        v.z = sd[r][sp[c4 * 4 + 2]];
        v.w = sd[r][sp[c4 * 4 + 3]];
        ob[(size_t)r * 64 + c4] = v;
    }
}

extern "C" void kernel_launch(void* const* d_in, const int* in_sizes, int n_in,
                              void* d_out, int out_size) {
    const float* D1 = (const float*)d_in[0];
    const float* D2 = (const float*)d_in[1];
    const int*   t1 = (const int*)d_in[2];
    const int*   t2 = (const int*)d_in[3];
    float* out = (float*)d_out;

    int B = in_sizes[0] / (NN * NN);
    if (B > MAXB) B = MAXB;

    dim3 cgr(B, 2);
    colsum_kernel<<<cgr, 256>>>(D1, D2);

    long long base = (long long)B * NN * NN;
    sort_kernel<<<B, NN>>>(t1, t2, out, base, (long long)out_size);

    dim3 ggrid(NN / GR, B);
    gather_kernel<<<ggrid, 256>>>(D1, out);
}

// round 13
// speedup vs baseline: 1.0282x; 1.0129x over previous
#include <cuda_runtime.h>
#include <cuda_bf16.h>
#include <stdint.h>

#define NN 256            // N (atoms per batch)
#define MAXB 512          // max batch
#define GR 16             // output rows per gather block
#define TK 16             // tile rows for colsum staging
#define NT (NN / TK)      // 16 tiles

__device__ int       g_perm[MAXB * NN];
__device__ float     g_ss1[MAXB * NN], g_v41[MAXB * NN];
__device__ long long g_vi1[MAXB * NN];
__device__ float     g_ss2[MAXB * NN], g_v42[MAXB * NN];
__device__ long long g_vi2[MAXB * NN];

// ---------------------------------------------------------------------------
// Reduction: block streams its 256KB matrix CONTIGUOUSLY through shared
// memory (cp.async double-buffered 16KB tiles), then each thread walks its
// column inside the tile. DRAM sees sequential streams (the pattern gather
// proves runs at ~4.7TB/s) instead of 1KB-strided column walks (2.25TB/s).
// Voter arithmetic per column BIT-IDENTICAL to passing R7-R12:
//   seq  : strict sequential chain over k
//   IC4  : a[k%4] accumulators in increasing k, left-chain combine
//   truth: exact fixed-point int64 (order-free)
// 256 threads/block, grid (B, 2).
// ---------------------------------------------------------------------------
__global__ __launch_bounds__(256) void colsum_kernel(const float* __restrict__ D1,
                                                     const float* __restrict__ D2) {
    const int b     = blockIdx.x;
    const int which = blockIdx.y;
    const int tid   = threadIdx.x;

    const float4* q = (const float4*)((which ? D2 : D1) + (size_t)b * NN * NN);
    float*     oss = (which ? g_ss2 : g_ss1) + b * NN;
    float*     ov4 = (which ? g_v42 : g_v41) + b * NN;
    long long* ovi = (which ? g_vi2 : g_vi1) + b * NN;

    __shared__ float tile[2][TK * NN];   // 2 x 16KB

    // Issue one 16KB tile load: 1024 float4 slots, 4 per thread, coalesced.
    #define LOAD_TILE(buf, t0)                                                 \
        {                                                                      \
            uint32_t _base = (uint32_t)__cvta_generic_to_shared(&tile[buf][0]);\
            _Pragma("unroll")                                                  \
            for (int m = 0; m < 4; ++m) {                                      \
                int idx = m * 256 + tid;                                       \
                asm volatile("cp.async.cg.shared.global [%0], [%1], 16;\n"     \
                             :: "r"(_base + idx * 16),                         \
                                "l"(q + (size_t)(t0) * 64 + idx)               \
                             : "memory");                                      \
            }                                                                  \
            asm volatile("cp.async.commit_group;\n" ::: "memory");             \
        }

    float ss = 0.f, a0 = 0.f, a1 = 0.f, a2 = 0.f, a3 = 0.f;
    long long acc = 0;
    const float SCALE = 1099511627776.0f;   // 2^40 (exact power-of-two scale)

    LOAD_TILE(0, 0);

#pragma unroll 1
    for (int ti = 0; ti < NT; ++ti) {
        if (ti + 1 < NT) {
            LOAD_TILE((ti + 1) & 1, (ti + 1) * TK);
            asm volatile("cp.async.wait_group 1;\n" ::: "memory");
        } else {
            asm volatile("cp.async.wait_group 0;\n" ::: "memory");
        }
        __syncthreads();

        const float* T = &tile[ti & 1][0];
        float x[TK];
#pragma unroll
        for (int r = 0; r < TK; ++r) x[r] = T[r * NN + tid];   // conflict-free

        // strict sequential chain (identical order to R7-R12)
#pragma unroll
        for (int r = 0; r < TK; ++r) ss = __fadd_rn(ss, x[r]);
        // IC4 round-robin: k = ti*16 + r, k%4 == r%4 (TK multiple of 4)
#pragma unroll
        for (int r = 0; r < TK; r += 4) {
            a0 = __fadd_rn(a0, x[r + 0]);
            a1 = __fadd_rn(a1, x[r + 1]);
            a2 = __fadd_rn(a2, x[r + 2]);
            a3 = __fadd_rn(a3, x[r + 3]);
        }
        // exact fixed-point truth (order-free)
#pragma unroll
        for (int r = 0; r < TK; ++r) acc += __float2ll_rn(x[r] * SCALE);

        __syncthreads();   // protect buffer before it is overwritten
    }
    #undef LOAD_TILE

    oss[tid] = ss;
    ov4[tid] = __fadd_rn(__fadd_rn(__fadd_rn(a0, a1), a2), a3);
    ovi[tid] = acc;
}

// ---------------------------------------------------------------------------
// Sort: bitonic lexsort per batch with majority comparator over the three
// voter orders (type primary; per-voter index tie-break). Also writes the
// gathered-types output tail.
// ---------------------------------------------------------------------------
__global__ void sort_kernel(const int* __restrict__ t1,
                            const int* __restrict__ t2,
                            float* __restrict__ out,
                            long long base, long long out_size) {
    const int b   = blockIdx.x;
    const int tid = threadIdx.x;

    __shared__ float     vs1[NN], v41[NN];
    __shared__ long long vi1[NN];
    __shared__ float     vs2[NN], v42[NN];
    __shared__ long long vi2[NN];
    __shared__ int       ty1s[NN], ty2s[NN];
    __shared__ int       idx1[NN], idx2[NN];

    vs1[tid] = g_ss1[b * NN + tid];
    v41[tid] = g_v41[b * NN + tid];
    vi1[tid] = g_vi1[b * NN + tid];
    vs2[tid] = g_ss2[b * NN + tid];
    v42[tid] = g_v42[b * NN + tid];
    vi2[tid] = g_vi2[b * NN + tid];
    ty1s[tid] = t1[b * NN + tid];
    ty2s[tid] = t2[b * NN + tid];
    idx1[tid] = tid;
    idx2[tid] = tid;
    __syncthreads();

    #define BEFORE(ty, vsq, v4a, vib, i, j, res)                              \
        {                                                                     \
            int _ti = ty[i], _tj = ty[j];                                     \
            if (_ti != _tj) { res = (_ti < _tj); }                            \
            else {                                                            \
                int _v = 0;                                                   \
                _v += (vsq[i] < vsq[j]) || (vsq[i] == vsq[j] && (i) < (j));   \
                _v += (v4a[i] < v4a[j]) || (v4a[i] == v4a[j] && (i) < (j));   \
                _v += (vib[i] < vib[j]) || (vib[i] == vib[j] && (i) < (j));   \
                res = (_v >= 2);                                              \
            }                                                                 \
        }

    for (int k = 2; k <= NN; k <<= 1) {
        for (int j = k >> 1; j > 0; j >>= 1) {
            int partner = tid ^ j;
            if (partner > tid) {
                bool up = ((tid & k) == 0);
                {
                    int ia = idx1[tid], ib = idx1[partner];
                    bool a_before_b;
                    BEFORE(ty1s, vs1, v41, vi1, ia, ib, a_before_b);
                    if (up == !a_before_b) { idx1[tid] = ib; idx1[partner] = ia; }
                }
                {
                    int ia = idx2[tid], ib = idx2[partner];
                    bool a_before_b;
                    BEFORE(ty2s, vs2, v42, vi2, ia, ib, a_before_b);
                    if (up == !a_before_b) { idx2[tid] = ib; idx2[partner] = ia; }
                }
            }
            __syncthreads();
        }
    }
    #undef BEFORE

    // perm[order2[t]] = order1[t]
    g_perm[b * NN + idx2[tid]] = idx1[tid];

    // gathered-types tail: out[base + b*NN + pos] = types1[source atom]
    long long o = base + (long long)b * NN + idx2[tid];
    if (o < out_size) out[o] = (float)ty1s[idx1[tid]];
}

// ---------------------------------------------------------------------------
// Gather: out[b,i,j] = D1[b, perm[i], perm[j]]. GR rows per block; float4
// loads AND float4 stores (4 shared gathers per 16B store).
// ---------------------------------------------------------------------------
__global__ void gather_kernel(const float* __restrict__ D1,
                              float* __restrict__ out) {
    const int b   = blockIdx.y;
    const int i0  = blockIdx.x * GR;
    const int tid = threadIdx.x;   // 256 threads

    __shared__ int   sp[NN];
    __shared__ float sd[GR][NN];

    sp[tid] = g_perm[b * NN + tid];
    __syncthreads();

    const float4* src4 = (const float4*)(D1 + (size_t)b * NN * NN);
#pragma unroll
    for (int m = 0; m < GR * 64 / 256; ++m) {
        int q  = m * 256 + tid;     // over GR*64 float4 slots
        int r  = q >> 6;            // row
        int c4 = q & 63;
        int s  = sp[i0 + r];
        ((float4*)sd[r])[c4] = src4[(size_t)s * 64 + c4];
    }
    __syncthreads();

    float4* ob = (float4*)(out + ((size_t)b * NN + i0) * NN);
#pragma unroll
    for (int m = 0; m < GR * 64 / 256; ++m) {
        int q  = m * 256 + tid;
        int r  = q >> 6;
        int c4 = q & 63;
        float4 v;
        v.x = sd[r][sp[c4 * 4 + 0]];
        v.y = sd[r][sp[c4 * 4 + 1]];
        v.z = sd[r][sp[c4 * 4 + 2]];
        v.w = sd[r][sp[c4 * 4 + 3]];
        ob[(size_t)r * 64 + c4] = v;
    }
}

extern "C" void kernel_launch(void* const* d_in, const int* in_sizes, int n_in,
                              void* d_out, int out_size) {
    const float* D1 = (const float*)d_in[0];
    const float* D2 = (const float*)d_in[1];
    const int*   t1 = (const int*)d_in[2];
    const int*   t2 = (const int*)d_in[3];
    float* out = (float*)d_out;

    int B = in_sizes[0] / (NN * NN);
    if (B > MAXB) B = MAXB;

    dim3 cgr(B, 2);
    colsum_kernel<<<cgr, 256>>>(D1, D2);

    long long base = (long long)B * NN * NN;
    sort_kernel<<<B, NN>>>(t1, t2, out, base, (long long)out_size);

    dim3 ggrid(NN / GR, B);
    gather_kernel<<<ggrid, 256>>>(D1, out);
}